// round 13
// baseline (speedup 1.0000x reference)
#include <cuda_runtime.h>
#include <math.h>
#include <float.h>

#define B    64
#define H    224
#define W    224
#define HW   (H*W)
#define NTOT (B*HW)
#define NC   196
#define NBR  10
#define WINS 20
#define ITERS 50
#define TPB  256

// propagation: region 96x96, central 80x80, 24 warps x (3 cols x 4 rows)/thread
#define PHALO 8
#define CEN   80
#define PRC   96
#define PRR   96
#define PWP   24
#define PRPW  4
#define PTPB3 768

// ---------------- scratch (static device globals) ---------------------------
__device__ float         g_wcd [4][NTOT];     // wgm + 10*cdiff[d]
__device__ float         g_dist[2][NTOT];
__device__ unsigned char g_mask[2][NTOT];

// ---------------- phase 1: fused gray/sobel/wgm/wcd + init (smem-tiled) ------
#define GT_W 34
#define GT_H 10

__global__ __launch_bounds__(256) void k_gradwcd(const float* __restrict__ x,
                                                 float* __restrict__ out_grad) {
    __shared__ float sc0[GT_H][GT_W];
    __shared__ float sc1[GT_H][GT_W];
    __shared__ float sc2[GT_H][GT_W];
    __shared__ float sgr[GT_H][GT_W];

    const int tid = threadIdx.x;
    const int ox = blockIdx.x * 32;
    const int oy = blockIdx.y * 8;
    const int b  = blockIdx.z;
    const float* xb = x + (size_t)b * 3 * HW;

    for (int idx = tid; idx < GT_W * GT_H; idx += 256) {
        int ly = idx / GT_W, lx = idx - ly * GT_W;
        int gy = oy - 1 + ly; gy += (gy < 0) ? H : 0; gy -= (gy >= H) ? H : 0;
        int gx = ox - 1 + lx; gx += (gx < 0) ? W : 0; gx -= (gx >= W) ? W : 0;
        int gi = gy * W + gx;
        float R = xb[gi], G = xb[HW + gi], Bv = xb[2 * HW + gi];
        sc0[ly][lx] = R; sc1[ly][lx] = G; sc2[ly][lx] = Bv;
        float t = __fadd_rn(__fmul_rn(0.2989f, R), __fmul_rn(0.587f, G));
        sgr[ly][lx] = __fadd_rn(t, __fmul_rn(0.114f, Bv));
    }
    __syncthreads();

    const int tx = tid & 31, ty = tid >> 5;
    const int y = oy + ty, xx = ox + tx;
    const int ly = ty + 1, lx = tx + 1;

    #define TAP(dy, dx) ((((unsigned)(y + (dy)) < (unsigned)H) && ((unsigned)(xx + (dx)) < (unsigned)W)) ? sgr[ly + (dy)][lx + (dx)] : 0.0f)
    float a00 = TAP(-1,-1), a01 = TAP(-1,0), a02 = TAP(-1,1);
    float a10 = TAP(0,-1),                   a12 = TAP(0,1);
    float a20 = TAP(1,-1),  a21 = TAP(1,0),  a22 = TAP(1,1);
    #undef TAP

    float gx2 = __fadd_rn(-a00, a02);
    gx2 = __fadd_rn(gx2, __fmul_rn(-2.0f, a10));
    gx2 = __fadd_rn(gx2, __fmul_rn( 2.0f, a12));
    gx2 = __fadd_rn(gx2, -a20);
    gx2 = __fadd_rn(gx2,  a22);
    float gy2 = __fadd_rn(-a00, __fmul_rn(-2.0f, a01));
    gy2 = __fadd_rn(gy2, -a02);
    gy2 = __fadd_rn(gy2,  a20);
    gy2 = __fadd_rn(gy2, __fmul_rn(2.0f, a21));
    gy2 = __fadd_rn(gy2,  a22);

    float s = __fadd_rn(__fadd_rn(__fmul_rn(gx2, gx2), __fmul_rn(gy2, gy2)), 1e-8f);
    float g = sqrtf(s);
    int gi = b * HW + y * W + xx;
    out_grad[gi] = g;
    float gg  = __fmul_rn(g, g);
    float g4  = __fmul_rn(gg, gg);
    float wgm = __fmul_rn(g4, 10.0f);

    float c0 = sc0[ly][lx], c1 = sc1[ly][lx], c2 = sc2[ly][lx];
    const int ndy[4] = {1, -1, 0, 0};
    const int ndx[4] = {0, 0, 1, -1};
#pragma unroll
    for (int d = 0; d < 4; d++) {
        int ny = ly + ndy[d], nx = lx + ndx[d];
        float sc = __fadd_rn(__fadd_rn(fabsf(c0 - sc0[ny][nx]), fabsf(c1 - sc1[ny][nx])),
                             fabsf(c2 - sc2[ny][nx]));
        g_wcd[d][gi] = __fadd_rn(wgm, __fmul_rn(sc, 10.0f));
    }
    g_dist[0][gi] = INFINITY;
    g_mask[0][gi] = 255;
}

// ---------------- phase 2: nearest-minima snap + seed scatter ----------------
#define OCCW ((HW + 31) / 32)

__device__ __forceinline__ float wredminf(float v) {
#pragma unroll
    for (int o = 16; o; o >>= 1) v = fminf(v, __shfl_xor_sync(0xffffffffu, v, o));
    return v;
}
__device__ __forceinline__ int wredmini(int v) {
#pragma unroll
    for (int o = 16; o; o >>= 1) v = min(v, __shfl_xor_sync(0xffffffffu, v, o));
    return v;
}

__global__ void k_cents(const float* __restrict__ grad, float* __restrict__ cents_out) {
    extern __shared__ unsigned char smraw[];
    float*        sg  = (float*)smraw;
    unsigned int* occ = (unsigned int*)(smraw + (size_t)HW * sizeof(float));
    __shared__ float smv[NC];
    __shared__ int   sli[NC];

    int b = blockIdx.x;
    int tid = threadIdx.x;
    const float* gb = grad + b * HW;
    for (int i = tid; i < HW; i += TPB) sg[i] = gb[i];
    for (int i = tid; i < OCCW; i += TPB) occ[i] = 0u;
    __syncthreads();

    int warp = tid >> 5, lane = tid & 31;
    for (int k = warp; k < NC; k += 8) {
        int cy = 8 + 16 * (k / 14);
        int cx = 8 + 16 * (k % 14);
        int ymin = max(0, cy - NBR), ymax = min(H, cy + NBR);
        int xmin = max(0, cx - NBR), xmax = min(W, cx + NBR);
        int h = ymax - ymin, w = xmax - xmin;

        float colmin = INFINITY;
        bool lv = (lane < w) && (lane < WINS);
        if (lv) {
            const float* col = sg + ymin * W + xmin + lane;
#pragma unroll
            for (int wy = 0; wy < WINS; wy++) {
                if (wy < h) colmin = fminf(colmin, col[wy * W]);
            }
        }
        float mv = wredminf(colmin);
        int li = WINS * WINS;
        if (lv) {
            const float* col = sg + ymin * W + xmin + lane;
#pragma unroll
            for (int wy = 0; wy < WINS; wy++) {
                if (wy < h && col[wy * W] == mv) { li = wy * WINS + lane; break; }
            }
        }
        li = wredmini(li);
        if (lane == 0) { smv[k] = mv; sli[k] = li; }
    }
    __syncthreads();

    if (warp == 0) {
        const int wy0 = lane / WINS;
        const int wx0 = lane - wy0 * WINS;
        for (int k = 0; k < NC; k++) {
            int cy = 8 + 16 * (k / 14);
            int cx = 8 + 16 * (k % 14);
            int ymin = max(0, cy - NBR), ymax = min(H, cy + NBR);
            int xmin = max(0, cx - NBR), xmax = min(W, cx + NBR);
            int h = ymax - ymin, w = xmax - xmin;
            int ny = cy, nx = cx;
            bool found = false;
            int li = sli[k];
            float mv = smv[k];
            if (li < WINS * WINS) {
                int py = ymin + li / WINS, px = xmin + li % WINS;
                int bi = py * W + px;
                bool occupied = (occ[bi >> 5] >> (bi & 31)) & 1u;
                if (!occupied) {
                    ny = py; nx = px; found = true;
                } else {
                    int best = WINS * WINS;
                    int wy = wy0, wx = wx0;
#pragma unroll
                    for (int t = 0; t < 13; t++) {
                        int idx = lane + 32 * t;
                        if (idx < WINS * WINS && wy < h && wx < w) {
                            int b2 = (ymin + wy) * W + (xmin + wx);
                            if (sg[b2] == mv && !((occ[b2 >> 5] >> (b2 & 31)) & 1u))
                                best = min(best, idx);
                        }
                        wx += 12; wy += 1;
                        if (wx >= WINS) { wx -= WINS; wy += 1; }
                    }
                    best = wredmini(best);
                    if (best < WINS * WINS) {
                        ny = ymin + best / WINS;
                        nx = xmin + best % WINS;
                        found = true;
                    }
                }
            }
            if (lane == 0) {
                if (found) {
                    int bi = ny * W + nx;
                    occ[bi >> 5] |= (1u << (bi & 31));
                }
                cents_out[(b * NC + k) * 2 + 0] = (float)ny;
                cents_out[(b * NC + k) * 2 + 1] = (float)nx;
                int gi = b * HW + ny * W + nx;
                g_dist[0][gi] = 0.0f;
                g_mask[0][gi] = (unsigned char)k;
            }
            __syncwarp();
        }
    }
}

// ---------------- phase 3: register-wcd jumbo-tile propagation ---------------
// 1 block/SM, 768 thr (24 warps). Lane owns 3 interleaved cols (3L..3L+2),
// warp owns 4 rows. wcd lives in 48 REGISTERS (no smem wc traffic). smem only
// for warp-boundary row exchange. 2 barriers/iter. Erosion 1 ring/iter.
__global__ __launch_bounds__(PTPB3, 1) void k_prop(int s, int niter, int last,
                                                   float* __restrict__ out_mask) {
    __shared__ float xAD[PWP][PRC];
    __shared__ float xBD[PWP][PRC];
    __shared__ int   xAM[PWP][PRC];
    __shared__ int   xBM[PWP][PRC];

    const int tid  = threadIdx.x;
    const int lane = tid & 31;
    const int w    = tid >> 5;
    const int ox = blockIdx.x * CEN;
    const int oy = blockIdx.y * CEN;
    const int b  = blockIdx.z;

    const float*         dIn = g_dist[s];
    const unsigned char* mIn = g_mask[s];

    float d[3][PRPW];
    int   m[3][PRPW];
    float wc[4][3][PRPW];

    // ---- load own pixels + wcd into registers (torus wrap) -------------------
    {
        int rowt[PRPW], colo[3];
#pragma unroll
        for (int r = 0; r < PRPW; r++) {
            int gy = oy - PHALO + w * PRPW + r;
            gy += (gy < 0) ? H : 0; gy -= (gy >= H) ? H : 0;
            rowt[r] = b * HW + gy * W;
        }
#pragma unroll
        for (int j = 0; j < 3; j++) {
            int gx = ox - PHALO + 3 * lane + j;
            gx += (gx < 0) ? W : 0; gx -= (gx >= W) ? W : 0;
            colo[j] = gx;
        }
#pragma unroll
        for (int j = 0; j < 3; j++)
#pragma unroll
            for (int r = 0; r < PRPW; r++) {
                int gi = rowt[r] + colo[j];
                d[j][r] = dIn[gi];
                m[j][r] = mIn[gi];
                wc[0][j][r] = g_wcd[0][gi];
                wc[1][j][r] = g_wcd[1][gi];
                wc[2][j][r] = g_wcd[2][gi];
                wc[3][j][r] = g_wcd[3][gi];
            }
    }

    const int cb = 3 * lane;

#pragma unroll 1
    for (int it = 0; it < niter; it++) {
        // ---- pass 0: dir (-1,0), read y+1, rows ascending --------------------
#pragma unroll
        for (int j = 0; j < 3; j++) { xAD[w][cb + j] = d[j][0]; xAM[w][cb + j] = m[j][0]; }
        __syncthreads();
#pragma unroll
        for (int r = 0; r < PRPW - 1; r++)
#pragma unroll
            for (int j = 0; j < 3; j++) {
                float f = __fadd_rn(d[j][r + 1], wc[0][j][r]);
                if (f < d[j][r]) { d[j][r] = f; m[j][r] = m[j][r + 1]; }
            }
#pragma unroll
        for (int j = 0; j < 3; j++) {
            float nd = (w < PWP - 1) ? xAD[w + 1][cb + j] : INFINITY;
            int   nm = (w < PWP - 1) ? xAM[w + 1][cb + j] : 0;
            float f = __fadd_rn(nd, wc[0][j][PRPW - 1]);
            if (f < d[j][PRPW - 1]) { d[j][PRPW - 1] = f; m[j][PRPW - 1] = nm; }
        }
        // ---- pass 1: dir (1,0), read y-1, rows descending ---------------------
#pragma unroll
        for (int j = 0; j < 3; j++) { xBD[w][cb + j] = d[j][PRPW - 1]; xBM[w][cb + j] = m[j][PRPW - 1]; }
        __syncthreads();
#pragma unroll
        for (int r = PRPW - 1; r > 0; r--)
#pragma unroll
            for (int j = 0; j < 3; j++) {
                float f = __fadd_rn(d[j][r - 1], wc[1][j][r]);
                if (f < d[j][r]) { d[j][r] = f; m[j][r] = m[j][r - 1]; }
            }
#pragma unroll
        for (int j = 0; j < 3; j++) {
            float nd = (w > 0) ? xBD[w - 1][cb + j] : INFINITY;
            int   nm = (w > 0) ? xBM[w - 1][cb + j] : 0;
            float f = __fadd_rn(nd, wc[1][j][0]);
            if (f < d[j][0]) { d[j][0] = f; m[j][0] = nm; }
        }
        // ---- pass 2: dir (0,-1), read x+1 -------------------------------------
#pragma unroll
        for (int r = 0; r < PRPW; r++) {
            float o0 = d[0][r], o1 = d[1][r], o2 = d[2][r];
            int   q0 = m[0][r], q1 = m[1][r], q2 = m[2][r];
            float sh = __shfl_down_sync(0xffffffffu, o0, 1);
            int   sq = __shfl_down_sync(0xffffffffu, q0, 1);
            float f0 = __fadd_rn(o1, wc[2][0][r]); if (f0 < o0) { d[0][r] = f0; m[0][r] = q1; }
            float f1 = __fadd_rn(o2, wc[2][1][r]); if (f1 < o1) { d[1][r] = f1; m[1][r] = q2; }
            float f2 = __fadd_rn(sh, wc[2][2][r]); if (f2 < o2) { d[2][r] = f2; m[2][r] = sq; }
        }
        // ---- pass 3: dir (0,1), read x-1 --------------------------------------
#pragma unroll
        for (int r = 0; r < PRPW; r++) {
            float o0 = d[0][r], o1 = d[1][r], o2 = d[2][r];
            int   q0 = m[0][r], q1 = m[1][r], q2 = m[2][r];
            float sh = __shfl_up_sync(0xffffffffu, o2, 1);
            int   sq = __shfl_up_sync(0xffffffffu, q2, 1);
            float f0 = __fadd_rn(sh, wc[3][0][r]); if (f0 < o0) { d[0][r] = f0; m[0][r] = sq; }
            float f1 = __fadd_rn(o0, wc[3][1][r]); if (f1 < o1) { d[1][r] = f1; m[1][r] = q0; }
            float f2 = __fadd_rn(o1, wc[3][2][r]); if (f2 < o2) { d[2][r] = f2; m[2][r] = q1; }
        }
    }

    // ---- store central CEN x CEN (per-pixel guards; overhang discarded) -------
    {
        float*         dOut = g_dist[s ^ 1];
        unsigned char* mOut = g_mask[s ^ 1];
#pragma unroll
        for (int r = 0; r < PRPW; r++) {
            int R = w * PRPW + r;
            int gyu = oy + R - PHALO;
            if (R >= PHALO && R < PHALO + CEN && gyu < H) {
#pragma unroll
                for (int j = 0; j < 3; j++) {
                    int lc = cb + j;
                    int gxu = ox + lc - PHALO;
                    if (lc >= PHALO && lc < PHALO + CEN && gxu < W) {
                        int gi = b * HW + gyu * W + gxu;
                        if (!last) {
                            dOut[gi] = d[j][r];
                            mOut[gi] = (unsigned char)m[j][r];
                        } else {
                            out_mask[gi] = (m[j][r] == 255) ? -1.0f : (float)m[j][r];
                        }
                    }
                }
            }
        }
    }
}

// ---------------- launch ------------------------------------------------------
extern "C" void kernel_launch(void* const* d_in, const int* in_sizes, int n_in,
                              void* d_out, int out_size) {
    const float* x = (const float*)d_in[0];
    float* out = (float*)d_out;
    float* out_grad  = out;                       // (B,1,H,W)
    float* out_cents = out + NTOT;                // (B,196,2)
    float* out_mask  = out + NTOT + B * NC * 2;   // (B,H,W)

    static const size_t centsSmem = (size_t)HW * sizeof(float) + (size_t)OCCW * sizeof(unsigned int);
    cudaFuncSetAttribute(k_cents, cudaFuncAttributeMaxDynamicSharedMemorySize, (int)centsSmem);

    dim3 gg(W / 32, H / 8, B);                    // 7 x 28 x 64
    k_gradwcd<<<gg, 256>>>(x, out_grad);
    k_cents  <<<B, TPB, centsSmem>>>(out_grad, out_cents);

    dim3 pg((W + CEN - 1) / CEN, (H + CEN - 1) / CEN, B);   // 3 x 3 x 64 = 576
    int s = 0;
    int remaining = ITERS;
    while (remaining > 0) {
        int it = remaining >= PHALO ? PHALO : remaining;
        remaining -= it;
        int last = (remaining == 0) ? 1 : 0;
        k_prop<<<pg, PTPB3>>>(s, it, last, out_mask);
        s ^= 1;
    }
}

// round 14
// speedup vs baseline: 1.0604x; 1.0604x over previous
#include <cuda_runtime.h>
#include <math.h>
#include <float.h>

#define B    64
#define H    224
#define W    224
#define HW   (H*W)
#define NTOT (B*HW)
#define NC   196
#define NBR  10
#define WINS 20
#define ITERS 50
#define TPB  256

// propagation: region 64x96, central 48x80; 32 warps x (2 cols x 3 rows)/thread
#define HALO  8
#define CC    48
#define CR    80
#define RC    64
#define RR    96
#define PWARPS 32
#define RPW   3
#define PTPB  1024

// ---------------- scratch (static device globals) ---------------------------
__device__ float         g_wcd [4][NTOT];     // wgm + 10*cdiff[d]
__device__ float         g_dist[2][NTOT];
__device__ unsigned char g_mask[2][NTOT];

// ---------------- phase 1: fused gray/sobel/wgm/wcd + init (smem-tiled) ------
#define GT_W 34
#define GT_H 10

__global__ __launch_bounds__(256) void k_gradwcd(const float* __restrict__ x,
                                                 float* __restrict__ out_grad) {
    __shared__ float sc0[GT_H][GT_W];
    __shared__ float sc1[GT_H][GT_W];
    __shared__ float sc2[GT_H][GT_W];
    __shared__ float sgr[GT_H][GT_W];

    const int tid = threadIdx.x;
    const int ox = blockIdx.x * 32;
    const int oy = blockIdx.y * 8;
    const int b  = blockIdx.z;
    const float* xb = x + (size_t)b * 3 * HW;

    for (int idx = tid; idx < GT_W * GT_H; idx += 256) {
        int ly = idx / GT_W, lx = idx - ly * GT_W;
        int gy = oy - 1 + ly; gy += (gy < 0) ? H : 0; gy -= (gy >= H) ? H : 0;
        int gx = ox - 1 + lx; gx += (gx < 0) ? W : 0; gx -= (gx >= W) ? W : 0;
        int gi = gy * W + gx;
        float R = xb[gi], G = xb[HW + gi], Bv = xb[2 * HW + gi];
        sc0[ly][lx] = R; sc1[ly][lx] = G; sc2[ly][lx] = Bv;
        float t = __fadd_rn(__fmul_rn(0.2989f, R), __fmul_rn(0.587f, G));
        sgr[ly][lx] = __fadd_rn(t, __fmul_rn(0.114f, Bv));
    }
    __syncthreads();

    const int tx = tid & 31, ty = tid >> 5;
    const int y = oy + ty, xx = ox + tx;
    const int ly = ty + 1, lx = tx + 1;

    #define TAP(dy, dx) ((((unsigned)(y + (dy)) < (unsigned)H) && ((unsigned)(xx + (dx)) < (unsigned)W)) ? sgr[ly + (dy)][lx + (dx)] : 0.0f)
    float a00 = TAP(-1,-1), a01 = TAP(-1,0), a02 = TAP(-1,1);
    float a10 = TAP(0,-1),                   a12 = TAP(0,1);
    float a20 = TAP(1,-1),  a21 = TAP(1,0),  a22 = TAP(1,1);
    #undef TAP

    float gx2 = __fadd_rn(-a00, a02);
    gx2 = __fadd_rn(gx2, __fmul_rn(-2.0f, a10));
    gx2 = __fadd_rn(gx2, __fmul_rn( 2.0f, a12));
    gx2 = __fadd_rn(gx2, -a20);
    gx2 = __fadd_rn(gx2,  a22);
    float gy2 = __fadd_rn(-a00, __fmul_rn(-2.0f, a01));
    gy2 = __fadd_rn(gy2, -a02);
    gy2 = __fadd_rn(gy2,  a20);
    gy2 = __fadd_rn(gy2, __fmul_rn(2.0f, a21));
    gy2 = __fadd_rn(gy2,  a22);

    float s = __fadd_rn(__fadd_rn(__fmul_rn(gx2, gx2), __fmul_rn(gy2, gy2)), 1e-8f);
    float g = sqrtf(s);
    int gi = b * HW + y * W + xx;
    out_grad[gi] = g;
    float gg  = __fmul_rn(g, g);
    float g4  = __fmul_rn(gg, gg);
    float wgm = __fmul_rn(g4, 10.0f);

    float c0 = sc0[ly][lx], c1 = sc1[ly][lx], c2 = sc2[ly][lx];
    const int ndy[4] = {1, -1, 0, 0};
    const int ndx[4] = {0, 0, 1, -1};
#pragma unroll
    for (int d = 0; d < 4; d++) {
        int ny = ly + ndy[d], nx = lx + ndx[d];
        float sc = __fadd_rn(__fadd_rn(fabsf(c0 - sc0[ny][nx]), fabsf(c1 - sc1[ny][nx])),
                             fabsf(c2 - sc2[ny][nx]));
        g_wcd[d][gi] = __fadd_rn(wgm, __fmul_rn(sc, 10.0f));
    }
    g_dist[0][gi] = INFINITY;
    g_mask[0][gi] = 255;
}

// ---------------- phase 2: nearest-minima snap + seed scatter ----------------
#define OCCW ((HW + 31) / 32)

__device__ __forceinline__ float wredminf(float v) {
#pragma unroll
    for (int o = 16; o; o >>= 1) v = fminf(v, __shfl_xor_sync(0xffffffffu, v, o));
    return v;
}
__device__ __forceinline__ int wredmini(int v) {
#pragma unroll
    for (int o = 16; o; o >>= 1) v = min(v, __shfl_xor_sync(0xffffffffu, v, o));
    return v;
}

__global__ void k_cents(const float* __restrict__ grad, float* __restrict__ cents_out) {
    extern __shared__ unsigned char smraw[];
    float*        sg  = (float*)smraw;
    unsigned int* occ = (unsigned int*)(smraw + (size_t)HW * sizeof(float));
    __shared__ float smv[NC];
    __shared__ int   sli[NC];

    int b = blockIdx.x;
    int tid = threadIdx.x;
    const float* gb = grad + b * HW;
    for (int i = tid; i < HW; i += TPB) sg[i] = gb[i];
    for (int i = tid; i < OCCW; i += TPB) occ[i] = 0u;
    __syncthreads();

    int warp = tid >> 5, lane = tid & 31;
    for (int k = warp; k < NC; k += 8) {
        int cy = 8 + 16 * (k / 14);
        int cx = 8 + 16 * (k % 14);
        int ymin = max(0, cy - NBR), ymax = min(H, cy + NBR);
        int xmin = max(0, cx - NBR), xmax = min(W, cx + NBR);
        int h = ymax - ymin, w = xmax - xmin;

        float colmin = INFINITY;
        bool lv = (lane < w) && (lane < WINS);
        if (lv) {
            const float* col = sg + ymin * W + xmin + lane;
#pragma unroll
            for (int wy = 0; wy < WINS; wy++) {
                if (wy < h) colmin = fminf(colmin, col[wy * W]);
            }
        }
        float mv = wredminf(colmin);
        int li = WINS * WINS;
        if (lv) {
            const float* col = sg + ymin * W + xmin + lane;
#pragma unroll
            for (int wy = 0; wy < WINS; wy++) {
                if (wy < h && col[wy * W] == mv) { li = wy * WINS + lane; break; }
            }
        }
        li = wredmini(li);
        if (lane == 0) { smv[k] = mv; sli[k] = li; }
    }
    __syncthreads();

    if (warp == 0) {
        const int wy0 = lane / WINS;
        const int wx0 = lane - wy0 * WINS;
        for (int k = 0; k < NC; k++) {
            int cy = 8 + 16 * (k / 14);
            int cx = 8 + 16 * (k % 14);
            int ymin = max(0, cy - NBR), ymax = min(H, cy + NBR);
            int xmin = max(0, cx - NBR), xmax = min(W, cx + NBR);
            int h = ymax - ymin, w = xmax - xmin;
            int ny = cy, nx = cx;
            bool found = false;
            int li = sli[k];
            float mv = smv[k];
            if (li < WINS * WINS) {
                int py = ymin + li / WINS, px = xmin + li % WINS;
                int bi = py * W + px;
                bool occupied = (occ[bi >> 5] >> (bi & 31)) & 1u;
                if (!occupied) {
                    ny = py; nx = px; found = true;
                } else {
                    int best = WINS * WINS;
                    int wy = wy0, wx = wx0;
#pragma unroll
                    for (int t = 0; t < 13; t++) {
                        int idx = lane + 32 * t;
                        if (idx < WINS * WINS && wy < h && wx < w) {
                            int b2 = (ymin + wy) * W + (xmin + wx);
                            if (sg[b2] == mv && !((occ[b2 >> 5] >> (b2 & 31)) & 1u))
                                best = min(best, idx);
                        }
                        wx += 12; wy += 1;
                        if (wx >= WINS) { wx -= WINS; wy += 1; }
                    }
                    best = wredmini(best);
                    if (best < WINS * WINS) {
                        ny = ymin + best / WINS;
                        nx = xmin + best % WINS;
                        found = true;
                    }
                }
            }
            if (lane == 0) {
                if (found) {
                    int bi = ny * W + nx;
                    occ[bi >> 5] |= (1u << (bi & 31));
                }
                cents_out[(b * NC + k) * 2 + 0] = (float)ny;
                cents_out[(b * NC + k) * 2 + 1] = (float)nx;
                int gi = b * HW + ny * W + nx;
                g_dist[0][gi] = 0.0f;
                g_mask[0][gi] = (unsigned char)k;
            }
            __syncwarp();
        }
    }
}

// ---------------- phase 3: reg-wcd, 32-warp, 2-col propagation ---------------
// 1024 thr, 1 block/SM (32 warps). Lane owns contiguous col pair (even base,
// wrap-safe). Warp owns 3 rows. wcd in 24 registers. smem = exchange rows only.
__global__ __launch_bounds__(PTPB, 1) void k_prop(int s, int niter, int last,
                                                  float* __restrict__ out_mask) {
    __shared__ float2 xAD[PWARPS][32];
    __shared__ float2 xBD[PWARPS][32];
    __shared__ uchar2 xAM[PWARPS][32];
    __shared__ uchar2 xBM[PWARPS][32];

    const int tid  = threadIdx.x;
    const int lane = tid & 31;
    const int w    = tid >> 5;
    const int ox = blockIdx.x * CC;
    const int oy = blockIdx.y * CR;
    const int b  = blockIdx.z;

    const float*         dIn = g_dist[s];
    const unsigned char* mIn = g_mask[s];

    float  d0[RPW], d1[RPW];
    int    m0[RPW], m1[RPW];
    float2 wc[4][RPW];

    // ---- load own column pair: dist/mask/wcd (torus wrap; pair stays aligned)
    int gx0 = ox - HALO + 2 * lane; gx0 += (gx0 < 0) ? W : 0; gx0 -= (gx0 >= W) ? W : 0;
#pragma unroll
    for (int r = 0; r < RPW; r++) {
        int R = w * RPW + r;
        int gy = oy - HALO + R; gy += (gy < 0) ? H : 0; gy -= (gy >= H) ? H : 0;
        int gi = b * HW + gy * W + gx0;
        float2 dv = *(const float2*)(dIn + gi);
        uchar2 mv = *(const uchar2*)(mIn + gi);
        d0[r] = dv.x; d1[r] = dv.y;
        m0[r] = mv.x; m1[r] = mv.y;
        wc[0][r] = *(const float2*)(&g_wcd[0][gi]);
        wc[1][r] = *(const float2*)(&g_wcd[1][gi]);
        wc[2][r] = *(const float2*)(&g_wcd[2][gi]);
        wc[3][r] = *(const float2*)(&g_wcd[3][gi]);
    }

#pragma unroll 1
    for (int it = 0; it < niter; it++) {
        // ---- pass 0: dir (-1,0), read y+1, rows ascending --------------------
        xAD[w][lane] = make_float2(d0[0], d1[0]);
        xAM[w][lane] = make_uchar2((unsigned char)m0[0], (unsigned char)m1[0]);
        __syncthreads();
#pragma unroll
        for (int r = 0; r < RPW - 1; r++) {
            float2 c = wc[0][r];
            float f0 = __fadd_rn(d0[r + 1], c.x); if (f0 < d0[r]) { d0[r] = f0; m0[r] = m0[r + 1]; }
            float f1 = __fadd_rn(d1[r + 1], c.y); if (f1 < d1[r]) { d1[r] = f1; m1[r] = m1[r + 1]; }
        }
        {
            float2 nd = (w < PWARPS - 1) ? xAD[w + 1][lane] : make_float2(INFINITY, INFINITY);
            uchar2 nm = (w < PWARPS - 1) ? xAM[w + 1][lane] : make_uchar2(0, 0);
            float2 c = wc[0][RPW - 1];
            float f0 = __fadd_rn(nd.x, c.x); if (f0 < d0[RPW - 1]) { d0[RPW - 1] = f0; m0[RPW - 1] = nm.x; }
            float f1 = __fadd_rn(nd.y, c.y); if (f1 < d1[RPW - 1]) { d1[RPW - 1] = f1; m1[RPW - 1] = nm.y; }
        }
        // ---- pass 1: dir (1,0), read y-1, rows descending ---------------------
        xBD[w][lane] = make_float2(d0[RPW - 1], d1[RPW - 1]);
        xBM[w][lane] = make_uchar2((unsigned char)m0[RPW - 1], (unsigned char)m1[RPW - 1]);
        __syncthreads();
#pragma unroll
        for (int r = RPW - 1; r > 0; r--) {
            float2 c = wc[1][r];
            float f0 = __fadd_rn(d0[r - 1], c.x); if (f0 < d0[r]) { d0[r] = f0; m0[r] = m0[r - 1]; }
            float f1 = __fadd_rn(d1[r - 1], c.y); if (f1 < d1[r]) { d1[r] = f1; m1[r] = m1[r - 1]; }
        }
        {
            float2 nd = (w > 0) ? xBD[w - 1][lane] : make_float2(INFINITY, INFINITY);
            uchar2 nm = (w > 0) ? xBM[w - 1][lane] : make_uchar2(0, 0);
            float2 c = wc[1][0];
            float f0 = __fadd_rn(nd.x, c.x); if (f0 < d0[0]) { d0[0] = f0; m0[0] = nm.x; }
            float f1 = __fadd_rn(nd.y, c.y); if (f1 < d1[0]) { d1[0] = f1; m1[0] = nm.y; }
        }
        // ---- pass 2: dir (0,-1), read x+1 -------------------------------------
#pragma unroll
        for (int r = 0; r < RPW; r++) {
            float o0 = d0[r], o1 = d1[r];
            int   q0 = m0[r], q1 = m1[r];
            float sh = __shfl_down_sync(0xffffffffu, o0, 1);
            int   sm = __shfl_down_sync(0xffffffffu, q0, 1);
            float2 c = wc[2][r];
            float f0 = __fadd_rn(o1, c.x); if (f0 < o0) { d0[r] = f0; m0[r] = q1; }
            float f1 = __fadd_rn(sh, c.y); if (f1 < o1) { d1[r] = f1; m1[r] = sm; }
        }
        // ---- pass 3: dir (0,1), read x-1 --------------------------------------
#pragma unroll
        for (int r = 0; r < RPW; r++) {
            float o0 = d0[r], o1 = d1[r];
            int   q0 = m0[r], q1 = m1[r];
            float sh = __shfl_up_sync(0xffffffffu, o1, 1);
            int   sm = __shfl_up_sync(0xffffffffu, q1, 1);
            float2 c = wc[3][r];
            float f1 = __fadd_rn(o0, c.y); if (f1 < o1) { d1[r] = f1; m1[r] = q0; }
            float f0 = __fadd_rn(sh, c.x); if (f0 < o0) { d0[r] = f0; m0[r] = sm; }
        }
    }

    // ---- store central CC x CR (lanes 4..27, rows 8..88; guard overhang) ------
    if (lane >= 4 && lane < 28) {
        int gxu = ox - HALO + 2 * lane;             // even, pair contiguous
        if (gxu < W) {
            if (!last) {
                float*         dOut = g_dist[s ^ 1];
                unsigned char* mOut = g_mask[s ^ 1];
#pragma unroll
                for (int r = 0; r < RPW; r++) {
                    int R = w * RPW + r;
                    int gyu = oy + R - HALO;
                    if (R >= HALO && R < HALO + CR && gyu < H) {
                        int gi = b * HW + gyu * W + gxu;
                        *(float2*)(dOut + gi) = make_float2(d0[r], d1[r]);
                        *(uchar2*)(mOut + gi) = make_uchar2((unsigned char)m0[r], (unsigned char)m1[r]);
                    }
                }
            } else {
#pragma unroll
                for (int r = 0; r < RPW; r++) {
                    int R = w * RPW + r;
                    int gyu = oy + R - HALO;
                    if (R >= HALO && R < HALO + CR && gyu < H) {
                        int gi = b * HW + gyu * W + gxu;
                        float v0 = (m0[r] == 255) ? -1.0f : (float)m0[r];
                        float v1 = (m1[r] == 255) ? -1.0f : (float)m1[r];
                        *(float2*)(out_mask + gi) = make_float2(v0, v1);
                    }
                }
            }
        }
    }
}

// ---------------- launch ------------------------------------------------------
extern "C" void kernel_launch(void* const* d_in, const int* in_sizes, int n_in,
                              void* d_out, int out_size) {
    const float* x = (const float*)d_in[0];
    float* out = (float*)d_out;
    float* out_grad  = out;                       // (B,1,H,W)
    float* out_cents = out + NTOT;                // (B,196,2)
    float* out_mask  = out + NTOT + B * NC * 2;   // (B,H,W)

    static const size_t centsSmem = (size_t)HW * sizeof(float) + (size_t)OCCW * sizeof(unsigned int);
    cudaFuncSetAttribute(k_cents, cudaFuncAttributeMaxDynamicSharedMemorySize, (int)centsSmem);

    dim3 gg(W / 32, H / 8, B);                    // 7 x 28 x 64
    k_gradwcd<<<gg, 256>>>(x, out_grad);
    k_cents  <<<B, TPB, centsSmem>>>(out_grad, out_cents);

    dim3 pg((W + CC - 1) / CC, (H + CR - 1) / CR, B);   // 5 x 3 x 64 = 960
    int s = 0;
    int remaining = ITERS;
    while (remaining > 0) {
        int it = remaining >= HALO ? HALO : remaining;
        remaining -= it;
        int last = (remaining == 0) ? 1 : 0;
        k_prop<<<pg, PTPB>>>(s, it, last, out_mask);
        s ^= 1;
    }
}

// round 15
// speedup vs baseline: 1.1688x; 1.1022x over previous
#include <cuda_runtime.h>
#include <math.h>
#include <float.h>

#define B    64
#define H    224
#define W    224
#define HW   (H*W)
#define NTOT (B*HW)
#define NC   196
#define NBR  10
#define WINS 20
#define ITERS 50
#define TPB  256

// propagation: region 64x48, central 48x32; 16 warps x (2 cols x 3 rows)/thread
// reg-wcd + 2 blocks/SM (512 thr) — R6 issue efficiency + R14 instruction count
#define HALO  8
#define CC    48
#define CR    32
#define RC    64
#define RR    48
#define PWARPS 16
#define RPW   3
#define PTPB  512

// ---------------- scratch (static device globals) ---------------------------
__device__ float         g_wcd [4][NTOT];     // wgm + 10*cdiff[d]
__device__ float         g_dist[2][NTOT];
__device__ unsigned char g_mask[2][NTOT];

// ---------------- phase 1: fused gray/sobel/wgm/wcd + init (smem-tiled) ------
#define GT_W 34
#define GT_H 10

__global__ __launch_bounds__(256) void k_gradwcd(const float* __restrict__ x,
                                                 float* __restrict__ out_grad) {
    __shared__ float sc0[GT_H][GT_W];
    __shared__ float sc1[GT_H][GT_W];
    __shared__ float sc2[GT_H][GT_W];
    __shared__ float sgr[GT_H][GT_W];

    const int tid = threadIdx.x;
    const int ox = blockIdx.x * 32;
    const int oy = blockIdx.y * 8;
    const int b  = blockIdx.z;
    const float* xb = x + (size_t)b * 3 * HW;

    for (int idx = tid; idx < GT_W * GT_H; idx += 256) {
        int ly = idx / GT_W, lx = idx - ly * GT_W;
        int gy = oy - 1 + ly; gy += (gy < 0) ? H : 0; gy -= (gy >= H) ? H : 0;
        int gx = ox - 1 + lx; gx += (gx < 0) ? W : 0; gx -= (gx >= W) ? W : 0;
        int gi = gy * W + gx;
        float R = xb[gi], G = xb[HW + gi], Bv = xb[2 * HW + gi];
        sc0[ly][lx] = R; sc1[ly][lx] = G; sc2[ly][lx] = Bv;
        float t = __fadd_rn(__fmul_rn(0.2989f, R), __fmul_rn(0.587f, G));
        sgr[ly][lx] = __fadd_rn(t, __fmul_rn(0.114f, Bv));
    }
    __syncthreads();

    const int tx = tid & 31, ty = tid >> 5;
    const int y = oy + ty, xx = ox + tx;
    const int ly = ty + 1, lx = tx + 1;

    #define TAP(dy, dx) ((((unsigned)(y + (dy)) < (unsigned)H) && ((unsigned)(xx + (dx)) < (unsigned)W)) ? sgr[ly + (dy)][lx + (dx)] : 0.0f)
    float a00 = TAP(-1,-1), a01 = TAP(-1,0), a02 = TAP(-1,1);
    float a10 = TAP(0,-1),                   a12 = TAP(0,1);
    float a20 = TAP(1,-1),  a21 = TAP(1,0),  a22 = TAP(1,1);
    #undef TAP

    float gx2 = __fadd_rn(-a00, a02);
    gx2 = __fadd_rn(gx2, __fmul_rn(-2.0f, a10));
    gx2 = __fadd_rn(gx2, __fmul_rn( 2.0f, a12));
    gx2 = __fadd_rn(gx2, -a20);
    gx2 = __fadd_rn(gx2,  a22);
    float gy2 = __fadd_rn(-a00, __fmul_rn(-2.0f, a01));
    gy2 = __fadd_rn(gy2, -a02);
    gy2 = __fadd_rn(gy2,  a20);
    gy2 = __fadd_rn(gy2, __fmul_rn(2.0f, a21));
    gy2 = __fadd_rn(gy2,  a22);

    float s = __fadd_rn(__fadd_rn(__fmul_rn(gx2, gx2), __fmul_rn(gy2, gy2)), 1e-8f);
    float g = sqrtf(s);
    int gi = b * HW + y * W + xx;
    out_grad[gi] = g;
    float gg  = __fmul_rn(g, g);
    float g4  = __fmul_rn(gg, gg);
    float wgm = __fmul_rn(g4, 10.0f);

    float c0 = sc0[ly][lx], c1 = sc1[ly][lx], c2 = sc2[ly][lx];
    const int ndy[4] = {1, -1, 0, 0};
    const int ndx[4] = {0, 0, 1, -1};
#pragma unroll
    for (int d = 0; d < 4; d++) {
        int ny = ly + ndy[d], nx = lx + ndx[d];
        float sc = __fadd_rn(__fadd_rn(fabsf(c0 - sc0[ny][nx]), fabsf(c1 - sc1[ny][nx])),
                             fabsf(c2 - sc2[ny][nx]));
        g_wcd[d][gi] = __fadd_rn(wgm, __fmul_rn(sc, 10.0f));
    }
    g_dist[0][gi] = INFINITY;
    g_mask[0][gi] = 255;
}

// ---------------- phase 2: nearest-minima snap + seed scatter ----------------
#define OCCW ((HW + 31) / 32)

__device__ __forceinline__ float wredminf(float v) {
#pragma unroll
    for (int o = 16; o; o >>= 1) v = fminf(v, __shfl_xor_sync(0xffffffffu, v, o));
    return v;
}
__device__ __forceinline__ int wredmini(int v) {
#pragma unroll
    for (int o = 16; o; o >>= 1) v = min(v, __shfl_xor_sync(0xffffffffu, v, o));
    return v;
}

__global__ void k_cents(const float* __restrict__ grad, float* __restrict__ cents_out) {
    extern __shared__ unsigned char smraw[];
    float*        sg  = (float*)smraw;
    unsigned int* occ = (unsigned int*)(smraw + (size_t)HW * sizeof(float));
    __shared__ float smv[NC];
    __shared__ int   sli[NC];

    int b = blockIdx.x;
    int tid = threadIdx.x;
    const float* gb = grad + b * HW;
    for (int i = tid; i < HW; i += TPB) sg[i] = gb[i];
    for (int i = tid; i < OCCW; i += TPB) occ[i] = 0u;
    __syncthreads();

    int warp = tid >> 5, lane = tid & 31;
    for (int k = warp; k < NC; k += 8) {
        int cy = 8 + 16 * (k / 14);
        int cx = 8 + 16 * (k % 14);
        int ymin = max(0, cy - NBR), ymax = min(H, cy + NBR);
        int xmin = max(0, cx - NBR), xmax = min(W, cx + NBR);
        int h = ymax - ymin, w = xmax - xmin;

        float colmin = INFINITY;
        bool lv = (lane < w) && (lane < WINS);
        if (lv) {
            const float* col = sg + ymin * W + xmin + lane;
#pragma unroll
            for (int wy = 0; wy < WINS; wy++) {
                if (wy < h) colmin = fminf(colmin, col[wy * W]);
            }
        }
        float mv = wredminf(colmin);
        int li = WINS * WINS;
        if (lv) {
            const float* col = sg + ymin * W + xmin + lane;
#pragma unroll
            for (int wy = 0; wy < WINS; wy++) {
                if (wy < h && col[wy * W] == mv) { li = wy * WINS + lane; break; }
            }
        }
        li = wredmini(li);
        if (lane == 0) { smv[k] = mv; sli[k] = li; }
    }
    __syncthreads();

    if (warp == 0) {
        const int wy0 = lane / WINS;
        const int wx0 = lane - wy0 * WINS;
        for (int k = 0; k < NC; k++) {
            int cy = 8 + 16 * (k / 14);
            int cx = 8 + 16 * (k % 14);
            int ymin = max(0, cy - NBR), ymax = min(H, cy + NBR);
            int xmin = max(0, cx - NBR), xmax = min(W, cx + NBR);
            int h = ymax - ymin, w = xmax - xmin;
            int ny = cy, nx = cx;
            bool found = false;
            int li = sli[k];
            float mv = smv[k];
            if (li < WINS * WINS) {
                int py = ymin + li / WINS, px = xmin + li % WINS;
                int bi = py * W + px;
                bool occupied = (occ[bi >> 5] >> (bi & 31)) & 1u;
                if (!occupied) {
                    ny = py; nx = px; found = true;
                } else {
                    int best = WINS * WINS;
                    int wy = wy0, wx = wx0;
#pragma unroll
                    for (int t = 0; t < 13; t++) {
                        int idx = lane + 32 * t;
                        if (idx < WINS * WINS && wy < h && wx < w) {
                            int b2 = (ymin + wy) * W + (xmin + wx);
                            if (sg[b2] == mv && !((occ[b2 >> 5] >> (b2 & 31)) & 1u))
                                best = min(best, idx);
                        }
                        wx += 12; wy += 1;
                        if (wx >= WINS) { wx -= WINS; wy += 1; }
                    }
                    best = wredmini(best);
                    if (best < WINS * WINS) {
                        ny = ymin + best / WINS;
                        nx = xmin + best % WINS;
                        found = true;
                    }
                }
            }
            if (lane == 0) {
                if (found) {
                    int bi = ny * W + nx;
                    occ[bi >> 5] |= (1u << (bi & 31));
                }
                cents_out[(b * NC + k) * 2 + 0] = (float)ny;
                cents_out[(b * NC + k) * 2 + 1] = (float)nx;
                int gi = b * HW + ny * W + nx;
                g_dist[0][gi] = 0.0f;
                g_mask[0][gi] = (unsigned char)k;
            }
            __syncwarp();
        }
    }
}

// ---------------- phase 3: reg-wcd, 512-thr (2 blocks/SM), 2-col propagation -
__global__ __launch_bounds__(PTPB, 2) void k_prop(int s, int niter, int last,
                                                  float* __restrict__ out_mask) {
    __shared__ float2 xAD[PWARPS][32];
    __shared__ float2 xBD[PWARPS][32];
    __shared__ uchar2 xAM[PWARPS][32];
    __shared__ uchar2 xBM[PWARPS][32];

    const int tid  = threadIdx.x;
    const int lane = tid & 31;
    const int w    = tid >> 5;
    const int ox = blockIdx.x * CC;
    const int oy = blockIdx.y * CR;
    const int b  = blockIdx.z;

    const float*         dIn = g_dist[s];
    const unsigned char* mIn = g_mask[s];

    float  d0[RPW], d1[RPW];
    int    m0[RPW], m1[RPW];
    float2 wc[4][RPW];

    // ---- load own column pair: dist/mask/wcd (torus wrap; pair stays aligned)
    int gx0 = ox - HALO + 2 * lane; gx0 += (gx0 < 0) ? W : 0; gx0 -= (gx0 >= W) ? W : 0;
#pragma unroll
    for (int r = 0; r < RPW; r++) {
        int R = w * RPW + r;
        int gy = oy - HALO + R; gy += (gy < 0) ? H : 0; gy -= (gy >= H) ? H : 0;
        int gi = b * HW + gy * W + gx0;
        float2 dv = *(const float2*)(dIn + gi);
        uchar2 mv = *(const uchar2*)(mIn + gi);
        d0[r] = dv.x; d1[r] = dv.y;
        m0[r] = mv.x; m1[r] = mv.y;
        wc[0][r] = *(const float2*)(&g_wcd[0][gi]);
        wc[1][r] = *(const float2*)(&g_wcd[1][gi]);
        wc[2][r] = *(const float2*)(&g_wcd[2][gi]);
        wc[3][r] = *(const float2*)(&g_wcd[3][gi]);
    }

#pragma unroll 1
    for (int it = 0; it < niter; it++) {
        // ---- pass 0: dir (-1,0), read y+1, rows ascending --------------------
        xAD[w][lane] = make_float2(d0[0], d1[0]);
        xAM[w][lane] = make_uchar2((unsigned char)m0[0], (unsigned char)m1[0]);
        __syncthreads();
#pragma unroll
        for (int r = 0; r < RPW - 1; r++) {
            float2 c = wc[0][r];
            float f0 = __fadd_rn(d0[r + 1], c.x); if (f0 < d0[r]) { d0[r] = f0; m0[r] = m0[r + 1]; }
            float f1 = __fadd_rn(d1[r + 1], c.y); if (f1 < d1[r]) { d1[r] = f1; m1[r] = m1[r + 1]; }
        }
        {
            float2 nd = (w < PWARPS - 1) ? xAD[w + 1][lane] : make_float2(INFINITY, INFINITY);
            uchar2 nm = (w < PWARPS - 1) ? xAM[w + 1][lane] : make_uchar2(0, 0);
            float2 c = wc[0][RPW - 1];
            float f0 = __fadd_rn(nd.x, c.x); if (f0 < d0[RPW - 1]) { d0[RPW - 1] = f0; m0[RPW - 1] = nm.x; }
            float f1 = __fadd_rn(nd.y, c.y); if (f1 < d1[RPW - 1]) { d1[RPW - 1] = f1; m1[RPW - 1] = nm.y; }
        }
        // ---- pass 1: dir (1,0), read y-1, rows descending ---------------------
        xBD[w][lane] = make_float2(d0[RPW - 1], d1[RPW - 1]);
        xBM[w][lane] = make_uchar2((unsigned char)m0[RPW - 1], (unsigned char)m1[RPW - 1]);
        __syncthreads();
#pragma unroll
        for (int r = RPW - 1; r > 0; r--) {
            float2 c = wc[1][r];
            float f0 = __fadd_rn(d0[r - 1], c.x); if (f0 < d0[r]) { d0[r] = f0; m0[r] = m0[r - 1]; }
            float f1 = __fadd_rn(d1[r - 1], c.y); if (f1 < d1[r]) { d1[r] = f1; m1[r] = m1[r - 1]; }
        }
        {
            float2 nd = (w > 0) ? xBD[w - 1][lane] : make_float2(INFINITY, INFINITY);
            uchar2 nm = (w > 0) ? xBM[w - 1][lane] : make_uchar2(0, 0);
            float2 c = wc[1][0];
            float f0 = __fadd_rn(nd.x, c.x); if (f0 < d0[0]) { d0[0] = f0; m0[0] = nm.x; }
            float f1 = __fadd_rn(nd.y, c.y); if (f1 < d1[0]) { d1[0] = f1; m1[0] = nm.y; }
        }
        // ---- pass 2: dir (0,-1), read x+1 -------------------------------------
#pragma unroll
        for (int r = 0; r < RPW; r++) {
            float o0 = d0[r], o1 = d1[r];
            int   q0 = m0[r], q1 = m1[r];
            float sh = __shfl_down_sync(0xffffffffu, o0, 1);
            int   sm = __shfl_down_sync(0xffffffffu, q0, 1);
            float2 c = wc[2][r];
            float f0 = __fadd_rn(o1, c.x); if (f0 < o0) { d0[r] = f0; m0[r] = q1; }
            float f1 = __fadd_rn(sh, c.y); if (f1 < o1) { d1[r] = f1; m1[r] = sm; }
        }
        // ---- pass 3: dir (0,1), read x-1 --------------------------------------
#pragma unroll
        for (int r = 0; r < RPW; r++) {
            float o0 = d0[r], o1 = d1[r];
            int   q0 = m0[r], q1 = m1[r];
            float sh = __shfl_up_sync(0xffffffffu, o1, 1);
            int   sm = __shfl_up_sync(0xffffffffu, q1, 1);
            float2 c = wc[3][r];
            float f1 = __fadd_rn(o0, c.y); if (f1 < o1) { d1[r] = f1; m1[r] = q0; }
            float f0 = __fadd_rn(sh, c.x); if (f0 < o0) { d0[r] = f0; m0[r] = sm; }
        }
    }

    // ---- store central CC x CR (lanes 4..27, rows 8..40; guard x overhang) ----
    if (lane >= 4 && lane < 28) {
        int gxu = ox - HALO + 2 * lane;             // even, pair contiguous
        if (gxu < W) {
            if (!last) {
                float*         dOut = g_dist[s ^ 1];
                unsigned char* mOut = g_mask[s ^ 1];
#pragma unroll
                for (int r = 0; r < RPW; r++) {
                    int R = w * RPW + r;
                    int gyu = oy + R - HALO;
                    if (R >= HALO && R < HALO + CR) {
                        int gi = b * HW + gyu * W + gxu;
                        *(float2*)(dOut + gi) = make_float2(d0[r], d1[r]);
                        *(uchar2*)(mOut + gi) = make_uchar2((unsigned char)m0[r], (unsigned char)m1[r]);
                    }
                }
            } else {
#pragma unroll
                for (int r = 0; r < RPW; r++) {
                    int R = w * RPW + r;
                    int gyu = oy + R - HALO;
                    if (R >= HALO && R < HALO + CR) {
                        int gi = b * HW + gyu * W + gxu;
                        float v0 = (m0[r] == 255) ? -1.0f : (float)m0[r];
                        float v1 = (m1[r] == 255) ? -1.0f : (float)m1[r];
                        *(float2*)(out_mask + gi) = make_float2(v0, v1);
                    }
                }
            }
        }
    }
}

// ---------------- launch ------------------------------------------------------
extern "C" void kernel_launch(void* const* d_in, const int* in_sizes, int n_in,
                              void* d_out, int out_size) {
    const float* x = (const float*)d_in[0];
    float* out = (float*)d_out;
    float* out_grad  = out;                       // (B,1,H,W)
    float* out_cents = out + NTOT;                // (B,196,2)
    float* out_mask  = out + NTOT + B * NC * 2;   // (B,H,W)

    static const size_t centsSmem = (size_t)HW * sizeof(float) + (size_t)OCCW * sizeof(unsigned int);
    cudaFuncSetAttribute(k_cents, cudaFuncAttributeMaxDynamicSharedMemorySize, (int)centsSmem);

    dim3 gg(W / 32, H / 8, B);                    // 7 x 28 x 64
    k_gradwcd<<<gg, 256>>>(x, out_grad);
    k_cents  <<<B, TPB, centsSmem>>>(out_grad, out_cents);

    dim3 pg((W + CC - 1) / CC, H / CR, B);        // 5 x 7 x 64 = 2240
    int s = 0;
    int remaining = ITERS;
    while (remaining > 0) {
        int it = remaining >= HALO ? HALO : remaining;
        remaining -= it;
        int last = (remaining == 0) ? 1 : 0;
        k_prop<<<pg, PTPB>>>(s, it, last, out_mask);
        s ^= 1;
    }
}